// round 1
// baseline (speedup 1.0000x reference)
#include <cuda_runtime.h>
#include <math.h>

// Problem constants (fixed by the dataset)
#define BB 8
#define NPB 1048576          // elements per batch row
#define ZDIM 1024
#define HID 16
#define CTAS_PER_B 64
#define TPB 256
#define ELEMS_PER_CTA (NPB / CTAS_PER_B)   // 16384

// Scratch: per-(batch,bucket) sums and counts. Device globals (no allocation).
__device__ float g_sums[BB * ZDIM];
__device__ float g_cnts[BB * ZDIM];

__global__ void fik_zero_kernel() {
    int i = blockIdx.x * blockDim.x + threadIdx.x;
    if (i < BB * ZDIM) { g_sums[i] = 0.0f; g_cnts[i] = 0.0f; }
}

__global__ __launch_bounds__(TPB) void fik_main_kernel(
    const float* __restrict__ X,   // (B, N)
    const float* __restrict__ Y,   // (B, N, 1)
    const float* __restrict__ Zb,  // (Z,)
    const float* __restrict__ W1,  // (3, HID) row-major
    const float* __restrict__ B1,  // (HID,)
    const float* __restrict__ G,   // gamma (HID,)
    const float* __restrict__ Be,  // beta (HID,)
    const float* __restrict__ W2,  // (HID, 1)
    const float* __restrict__ B2)  // (1,)
{
    __shared__ float s_z[ZDIM];
    __shared__ float s_sum[ZDIM];
    __shared__ float s_cnt[ZDIM];
    __shared__ float s_w1[3][HID];
    __shared__ float s_b1[HID], s_g[HID], s_be[HID], s_w2[HID];
    __shared__ float s_b2;

    const int tid = threadIdx.x;

    for (int i = tid; i < ZDIM; i += TPB) {
        s_z[i]   = Zb[i];
        s_sum[i] = 0.0f;
        s_cnt[i] = 0.0f;
    }
    if (tid < 3 * HID) s_w1[tid / HID][tid % HID] = W1[tid];
    if (tid < HID) {
        s_b1[tid] = B1[tid];
        s_g[tid]  = G[tid];
        s_be[tid] = Be[tid];
        s_w2[tid] = W2[tid];
    }
    if (tid == 0) s_b2 = B2[0];
    __syncthreads();

    const int b = blockIdx.y;
    const long base = (long)b * NPB + (long)blockIdx.x * ELEMS_PER_CTA;

    const float z0  = s_z[0];
    const float dz  = s_z[1] - s_z[0];
    const float dzh = dz * 0.5f;     // matches reference's dz / 2 in f32

    for (int i = tid; i < ELEMS_PER_CTA; i += TPB) {
        const float xv = X[base + i];
        const float yv = Y[base + i];

        // idx = ceil((x - z0 - dz/2) / dz), mirrored in fp32 op-for-op
        float t = (xv - z0 - dzh) / dz;
        int idx = (int)ceilf(t);
        idx = min(max(idx, 0), ZDIM - 1);
        const float zg = s_z[idx];

        // h = [x, zg, y] @ W1 + b1
        float h[HID];
        float sum = 0.0f;
        #pragma unroll
        for (int j = 0; j < HID; j++) {
            float v = fmaf(xv, s_w1[0][j],
                      fmaf(zg, s_w1[1][j],
                      fmaf(yv, s_w1[2][j], s_b1[j])));
            h[j] = v;
            sum += v;
        }
        const float mu = sum * (1.0f / HID);

        // two-pass population variance (matches h.var(-1))
        float var = 0.0f;
        #pragma unroll
        for (int j = 0; j < HID; j++) {
            float d = h[j] - mu;
            var = fmaf(d, d, var);
        }
        var *= (1.0f / HID);
        const float rs = rsqrtf(var + 1e-5f);

        // LN affine -> exact-erf gelu -> dot W2
        float acc = 0.0f;
        #pragma unroll
        for (int j = 0; j < HID; j++) {
            float hn = fmaf((h[j] - mu) * rs, s_g[j], s_be[j]);
            float gl = 0.5f * hn * (1.0f + erff(hn * 0.7071067811865476f));
            acc = fmaf(gl, s_w2[j], acc);
        }
        const float out = (acc + s_b2) * yv;

        atomicAdd(&s_sum[idx], out);
        atomicAdd(&s_cnt[idx], 1.0f);
    }
    __syncthreads();

    // Flush per-CTA partials to global scratch
    for (int i = tid; i < ZDIM; i += TPB) {
        float c = s_cnt[i];
        if (c != 0.0f) {
            atomicAdd(&g_sums[b * ZDIM + i], s_sum[i]);
            atomicAdd(&g_cnts[b * ZDIM + i], c);
        }
    }
}

__global__ void fik_finalize_kernel(float* __restrict__ out) {
    int i = blockIdx.x * blockDim.x + threadIdx.x;
    if (i < BB * ZDIM) {
        // output (B, IN_DIM=1, Z) == flat (B*Z)
        out[i] = g_sums[i] / fmaxf(g_cnts[i], 1.0f);
    }
}

extern "C" void kernel_launch(void* const* d_in, const int* in_sizes, int n_in,
                              void* d_out, int out_size) {
    const float* X  = (const float*)d_in[0];
    const float* Y  = (const float*)d_in[1];
    const float* Zb = (const float*)d_in[2];
    const float* W1 = (const float*)d_in[3];
    const float* B1 = (const float*)d_in[4];
    const float* G  = (const float*)d_in[5];
    const float* Be = (const float*)d_in[6];
    const float* W2 = (const float*)d_in[7];
    const float* B2 = (const float*)d_in[8];
    float* out = (float*)d_out;

    fik_zero_kernel<<<(BB * ZDIM + 255) / 256, 256>>>();
    dim3 grid(CTAS_PER_B, BB);
    fik_main_kernel<<<grid, TPB>>>(X, Y, Zb, W1, B1, G, Be, W2, B2);
    fik_finalize_kernel<<<(BB * ZDIM + 255) / 256, 256>>>(out);
}

// round 2
// speedup vs baseline: 1.4762x; 1.4762x over previous
#include <cuda_runtime.h>
#include <math.h>

// Problem constants (fixed by the dataset)
#define BB 8
#define NPB 1048576          // elements per batch row
#define ZDIM 1024
#define HID 16
#define NPAIR (HID / 2)
#define CTAS_PER_B 64
#define TPB 256
#define ELEMS_PER_CTA (NPB / CTAS_PER_B)     // 16384
#define VEC 4
#define ITERS (ELEMS_PER_CTA / (TPB * VEC))  // 16

typedef unsigned long long ull;

// ---------- packed f32x2 helpers ----------
__device__ __forceinline__ ull pk2(float lo, float hi) {
    ull r;
    asm("mov.b64 %0, {%1, %2};" : "=l"(r) : "r"(__float_as_uint(lo)), "r"(__float_as_uint(hi)));
    return r;
}
__device__ __forceinline__ void upk2(ull p, float& lo, float& hi) {
    unsigned int a, b;
    asm("mov.b64 {%0, %1}, %2;" : "=r"(a), "=r"(b) : "l"(p));
    lo = __uint_as_float(a); hi = __uint_as_float(b);
}
__device__ __forceinline__ ull fma2_(ull a, ull b, ull c) {
    ull d; asm("fma.rn.f32x2 %0, %1, %2, %3;" : "=l"(d) : "l"(a), "l"(b), "l"(c)); return d;
}
__device__ __forceinline__ ull mul2_(ull a, ull b) {
    ull d; asm("mul.rn.f32x2 %0, %1, %2;" : "=l"(d) : "l"(a), "l"(b)); return d;
}
__device__ __forceinline__ ull add2_(ull a, ull b) {
    ull d; asm("add.rn.f32x2 %0, %1, %2;" : "=l"(d) : "l"(a), "l"(b)); return d;
}
__device__ __forceinline__ float rcp_(float x) {
    float r; asm("rcp.approx.ftz.f32 %0, %1;" : "=f"(r) : "f"(x)); return r;
}
__device__ __forceinline__ float rsq_(float x) {
    float r; asm("rsqrt.approx.ftz.f32 %0, %1;" : "=f"(r) : "f"(x)); return r;
}

// Scratch: per-(batch,bucket) sums and counts (no allocation allowed).
__device__ float g_sums[BB * ZDIM];
__device__ float g_cnts[BB * ZDIM];

__global__ void fik_zero_kernel() {
    int i = blockIdx.x * blockDim.x + threadIdx.x;
    if (i < BB * ZDIM) { g_sums[i] = 0.0f; g_cnts[i] = 0.0f; }
}

__global__ __launch_bounds__(TPB, 2) void fik_main_kernel(
    const float* __restrict__ X,   // (B, N)
    const float* __restrict__ Y,   // (B, N, 1)
    const float* __restrict__ Zb,  // (Z,)
    const float* __restrict__ W1,  // (3, HID) row-major
    const float* __restrict__ B1,  // (HID,)
    const float* __restrict__ G,   // gamma (HID,)
    const float* __restrict__ Be,  // beta (HID,)
    const float* __restrict__ W2,  // (HID, 1)
    const float* __restrict__ B2)  // (1,)
{
    __shared__ __align__(8) float s_z[ZDIM];
    __shared__ float s_sum[ZDIM];
    __shared__ float s_cnt[ZDIM];
    __shared__ __align__(8) float s_w1[3][HID];
    __shared__ __align__(8) float s_b1[HID], s_g[HID], s_be[HID], s_w2[HID];
    __shared__ float s_b2;

    const int tid = threadIdx.x;

    for (int i = tid; i < ZDIM; i += TPB) {
        s_z[i]   = Zb[i];
        s_sum[i] = 0.0f;
        s_cnt[i] = 0.0f;
    }
    if (tid < 3 * HID) s_w1[tid / HID][tid % HID] = W1[tid];
    if (tid < HID) {
        s_b1[tid] = B1[tid];
        s_g[tid]  = G[tid];
        s_be[tid] = Be[tid];
        s_w2[tid] = W2[tid];
    }
    if (tid == 0) s_b2 = B2[0];
    __syncthreads();

    // pair-packed views of the weights (broadcast LDS.64)
    const ull* w10 = (const ull*)s_w1[0];
    const ull* w11 = (const ull*)s_w1[1];
    const ull* w12 = (const ull*)s_w1[2];
    const ull* b1p = (const ull*)s_b1;
    const ull* gp  = (const ull*)s_g;
    const ull* bep = (const ull*)s_be;
    const ull* w2p = (const ull*)s_w2;

    const int b = blockIdx.y;
    const long base = (long)b * NPB + (long)blockIdx.x * ELEMS_PER_CTA;
    const float4* X4 = (const float4*)(X + base);
    const float4* Y4 = (const float4*)(Y + base);

    const float z0  = s_z[0];
    const float dz  = s_z[1] - s_z[0];
    const float dzh = dz * 0.5f;
    const float inv_dz = 1.0f / dz;   // exact div once; per-element mul thereafter
    const float b2s = s_b2;

    // Eigen/XLA rational erf coefficients, packed (both halves equal)
    const ull A13 = pk2(-2.72614225801306e-10f, -2.72614225801306e-10f);
    const ull A11 = pk2( 2.77068142495902e-08f,  2.77068142495902e-08f);
    const ull A9  = pk2(-2.10102402082508e-06f, -2.10102402082508e-06f);
    const ull A7  = pk2(-5.69250639462346e-05f, -5.69250639462346e-05f);
    const ull A5  = pk2(-7.34990630326855e-04f, -7.34990630326855e-04f);
    const ull A3  = pk2(-2.95459980854025e-03f, -2.95459980854025e-03f);
    const ull A1  = pk2(-1.60960333262415e-02f, -1.60960333262415e-02f);
    const ull Bq8 = pk2(-1.45660718464996e-05f, -1.45660718464996e-05f);
    const ull Bq6 = pk2(-2.13374055278905e-04f, -2.13374055278905e-04f);
    const ull Bq4 = pk2(-1.68282697438203e-03f, -1.68282697438203e-03f);
    const ull Bq2 = pk2(-7.37332916720468e-03f, -7.37332916720468e-03f);
    const ull Bq0 = pk2(-1.42647390514189e-02f, -1.42647390514189e-02f);
    const ull CIS2  = pk2(0.7071067811865476f, 0.7071067811865476f);
    const ull CHALF = pk2(0.5f, 0.5f);

    #pragma unroll 1
    for (int it = 0; it < ITERS; it++) {
        const int vidx = it * TPB + tid;
        const float4 xv4 = X4[vidx];
        const float4 yv4 = Y4[vidx];

        #pragma unroll
        for (int e = 0; e < VEC; e++) {
            const float xv = (e == 0) ? xv4.x : (e == 1) ? xv4.y : (e == 2) ? xv4.z : xv4.w;
            const float yv = (e == 0) ? yv4.x : (e == 1) ? yv4.y : (e == 2) ? yv4.z : yv4.w;

            // bucket index: ceil((x - z0 - dz/2) / dz)  (div -> recip-mul)
            float t = ((xv - z0) - dzh) * inv_dz;
            int idx = (int)ceilf(t);
            idx = min(max(idx, 0), ZDIM - 1);
            const float zg = s_z[idx];

            const ull x2 = pk2(xv, xv);
            const ull z2 = pk2(zg, zg);
            const ull y2 = pk2(yv, yv);

            // h = [x, zg, y] @ W1 + b1  (8 packed pairs)
            ull h[NPAIR];
            #pragma unroll
            for (int p = 0; p < NPAIR; p++) {
                h[p] = fma2_(x2, w10[p], fma2_(z2, w11[p], fma2_(y2, w12[p], b1p[p])));
            }

            // mean
            ull sa = add2_(add2_(h[0], h[1]), add2_(h[2], h[3]));
            ull sb = add2_(add2_(h[4], h[5]), add2_(h[6], h[7]));
            ull sp = add2_(sa, sb);
            float slo, shi; upk2(sp, slo, shi);
            const float mu = (slo + shi) * (1.0f / HID);
            const ull nmu = pk2(-mu, -mu);

            // deviations + variance
            ull vacc;
            #pragma unroll
            for (int p = 0; p < NPAIR; p++) {
                ull d = add2_(h[p], nmu);
                h[p] = d;                      // h[] now holds deviations
                vacc = (p == 0) ? mul2_(d, d) : fma2_(d, d, vacc);
            }
            {
                // fold packed accumulator
                float vlo, vhi; upk2(vacc, vlo, vhi);
                const float var = (vlo + vhi) * (1.0f / HID);
                const float rs = rsq_(var + 1e-5f);
                const ull rs2 = pk2(rs, rs);

                // LN affine -> rational-erf gelu -> dot W2
                ull acc = 0ULL;   // (0.0f, 0.0f)
                #pragma unroll
                for (int p = 0; p < NPAIR; p++) {
                    const ull hn = fma2_(mul2_(h[p], rs2), gp[p], bep[p]);
                    const ull arg = mul2_(hn, CIS2);
                    const ull s = mul2_(arg, arg);
                    ull pn = fma2_(s, A13, A11);
                    pn = fma2_(s, pn, A9);
                    pn = fma2_(s, pn, A7);
                    pn = fma2_(s, pn, A5);
                    pn = fma2_(s, pn, A3);
                    pn = fma2_(s, pn, A1);
                    pn = mul2_(pn, arg);           // numerator: arg * P(arg^2)
                    ull q = fma2_(s, Bq8, Bq6);
                    q = fma2_(s, q, Bq4);
                    q = fma2_(s, q, Bq2);
                    q = fma2_(s, q, Bq0);          // Q(arg^2) < 0 for all s >= 0
                    float q0, q1; upk2(q, q0, q1);
                    const ull rq = pk2(rcp_(q0), rcp_(q1));
                    const ull erf2 = mul2_(pn, rq);
                    const ull th = mul2_(hn, CHALF);
                    const ull ge = fma2_(th, erf2, th);   // 0.5*hn*(1+erf)
                    acc = fma2_(ge, w2p[p], acc);
                }
                float alo, ahi; upk2(acc, alo, ahi);
                const float out = (alo + ahi + b2s) * yv;

                atomicAdd(&s_sum[idx], out);
                atomicAdd(&s_cnt[idx], 1.0f);
            }
        }
    }
    __syncthreads();

    // Flush per-CTA partials to global scratch
    for (int i = tid; i < ZDIM; i += TPB) {
        float c = s_cnt[i];
        if (c != 0.0f) {
            atomicAdd(&g_sums[b * ZDIM + i], s_sum[i]);
            atomicAdd(&g_cnts[b * ZDIM + i], c);
        }
    }
}

__global__ void fik_finalize_kernel(float* __restrict__ out) {
    int i = blockIdx.x * blockDim.x + threadIdx.x;
    if (i < BB * ZDIM) {
        // output (B, IN_DIM=1, Z) == flat (B*Z)
        out[i] = g_sums[i] / fmaxf(g_cnts[i], 1.0f);
    }
}

extern "C" void kernel_launch(void* const* d_in, const int* in_sizes, int n_in,
                              void* d_out, int out_size) {
    const float* X  = (const float*)d_in[0];
    const float* Y  = (const float*)d_in[1];
    const float* Zb = (const float*)d_in[2];
    const float* W1 = (const float*)d_in[3];
    const float* B1 = (const float*)d_in[4];
    const float* G  = (const float*)d_in[5];
    const float* Be = (const float*)d_in[6];
    const float* W2 = (const float*)d_in[7];
    const float* B2 = (const float*)d_in[8];
    float* out = (float*)d_out;

    fik_zero_kernel<<<(BB * ZDIM + 255) / 256, 256>>>();
    dim3 grid(CTAS_PER_B, BB);
    fik_main_kernel<<<grid, TPB>>>(X, Y, Zb, W1, B1, G, Be, W2, B2);
    fik_finalize_kernel<<<(BB * ZDIM + 255) / 256, 256>>>(out);
}